// round 6
// baseline (speedup 1.0000x reference)
#include <cuda_runtime.h>
#include <cstdint>

#define NC    192
#define HW    56
#define PLANE (HW*HW)
#define SH_W  63             // 62 used + 1 pad -> conflict-free banks for C=7 strips
#define SH_H  62
#define NT    224            // 28 row-groups (R=2) x 8 col-groups (C=7)

typedef unsigned long long u64;

__device__ __forceinline__ u64 pack2(float lo, float hi) {
    return (u64)__float_as_uint(lo) | ((u64)__float_as_uint(hi) << 32);
}

__device__ __forceinline__ u64 ffma2(u64 a, u64 b, u64 c) {
    u64 d;
    asm("fma.rn.f32x2 %0, %1, %2, %3;" : "=l"(d) : "l"(a), "l"(b), "l"(c));
    return d;
}

// mantissa_map: a = |v|+1e-7 (always normal); m = mantissa(a) in [1,2);
// M = m>=1.5 ? m/2 : m   (== reference piecewise map, values in [0.75,1.5))
__device__ __forceinline__ float mant_map(float v) {
    float a = fabsf(v) + 1e-7f;
    unsigned u = __float_as_uint(a);
    float m = __uint_as_float((u & 0x007FFFFFu) | 0x3F800000u);
    return (m >= 1.5f) ? m * 0.5f : m;
}

__global__ void __launch_bounds__(NT, 3)
appro_waconv_kernel(const float* __restrict__ x,
                    const float* __restrict__ w,
                    float* __restrict__ out)
{
    __shared__ u64 sh[SH_H * SH_W];      // (x, x/M1) packed, zero halo
    __shared__ u64 shw[7 * 8];           // (A, w-A), rows padded to 8 for LDS.128

    const int plane = blockIdx.x;            // b*NC + c : one full 56x56 plane
    const int c     = plane % NC;
    const int tid   = threadIdx.x;           // 0..223

    const float* __restrict__ xin = x + (size_t)plane * PLANE;

    // --- weights: A = w/M2, B = w - A (padded layout [7][8]) ---
    if (tid < 56) {
        int k = tid >> 3, j = tid & 7;
        u64 v = 0ull;
        if (j < 7) {
            float wv = w[c * 49 + k * 7 + j];
            float M2 = mant_map(wv);
            float A  = wv / M2;
            v = pack2(A, wv - A);
        }
        shw[tid] = v;
    }

    // --- input halo tile: packed (x, x/M1); zeros in 3-wide pad + col 62 ---
    for (int cell = tid; cell < SH_H * SH_W; cell += NT) {
        int hy = cell / SH_W;
        int hx = cell - hy * SH_W;
        int iy = hy - 3, ix = hx - 3;
        u64 v = 0ull;
        if ((unsigned)iy < (unsigned)HW && (unsigned)ix < (unsigned)HW) {
            float xv = __ldg(&xin[iy * HW + ix]);
            float M1 = mant_map(xv);
            v = pack2(xv, __fdividef(xv, M1));
        }
        sh[cell] = v;
    }
    __syncthreads();

    const int cg = tid & 7;                  // col group: cols [cg*7, cg*7+7)
    const int rg = tid >> 3;                 // row group: rows {rg*2, rg*2+1}

    u64 acc0[7], acc1[7];
#pragma unroll
    for (int cc = 0; cc < 7; ++cc) { acc0[cc] = 0ull; acc1[cc] = 0ull; }

    const u64* __restrict__ base = &sh[(rg * 2) * SH_W + cg * 7];
    const ulonglong2* __restrict__ wq = (const ulonglong2*)shw;

    // 8 input rows feed 2 output rows; weight rows via LDS.128 broadcast
#pragma unroll
    for (int r = 0; r < 8; ++r) {
        u64 p[13];
#pragma unroll
        for (int m = 0; m < 13; ++m) p[m] = base[r * SH_W + m];

        if (r <= 6) {   // weight row k = r -> acc0 (o = 0)
            ulonglong2 q0 = wq[r*4+0], q1 = wq[r*4+1], q2 = wq[r*4+2], q3 = wq[r*4+3];
            u64 wj[7] = {q0.x, q0.y, q1.x, q1.y, q2.x, q2.y, q3.x};
#pragma unroll
            for (int j = 0; j < 7; ++j)
#pragma unroll
                for (int cc = 0; cc < 7; ++cc)
                    acc0[cc] = ffma2(p[cc + j], wj[j], acc0[cc]);
        }
        if (r >= 1) {   // weight row k = r-1 -> acc1 (o = 1)
            int k = r - 1;
            ulonglong2 q0 = wq[k*4+0], q1 = wq[k*4+1], q2 = wq[k*4+2], q3 = wq[k*4+3];
            u64 wj[7] = {q0.x, q0.y, q1.x, q1.y, q2.x, q2.y, q3.x};
#pragma unroll
            for (int j = 0; j < 7; ++j)
#pragma unroll
                for (int cc = 0; cc < 7; ++cc)
                    acc1[cc] = ffma2(p[cc + j], wj[j], acc1[cc]);
        }
    }

    float* __restrict__ o = out + (size_t)plane * PLANE + (rg * 2) * HW + cg * 7;
#pragma unroll
    for (int cc = 0; cc < 7; ++cc) {
        float lo = __uint_as_float((unsigned)(acc0[cc] & 0xFFFFFFFFull));
        float hi = __uint_as_float((unsigned)(acc0[cc] >> 32));
        o[cc] = lo + hi;
    }
#pragma unroll
    for (int cc = 0; cc < 7; ++cc) {
        float lo = __uint_as_float((unsigned)(acc1[cc] & 0xFFFFFFFFull));
        float hi = __uint_as_float((unsigned)(acc1[cc] >> 32));
        o[HW + cc] = lo + hi;
    }
}

extern "C" void kernel_launch(void* const* d_in, const int* in_sizes, int n_in,
                              void* d_out, int out_size)
{
    const float* x = (const float*)d_in[0];      // (4,192,56,56) fp32
    const float* w = (const float*)d_in[1];      // (192,1,7,7)   fp32
    float* out = (float*)d_out;                  // (4,192,56,56) fp32

    appro_waconv_kernel<<<4 * NC, NT>>>(x, w, out);
}

// round 7
// speedup vs baseline: 1.4117x; 1.4117x over previous
#include <cuda_runtime.h>
#include <cstdint>

#define NC    192
#define HW    56
#define PLANE (HW*HW)
#define SH_W  63             // 62 used + 1 pad -> conflict-free for C=7 strips
#define SH_H  62
#define NT    224            // 28 row-groups (R=2) x 8 col-groups (C=7)

typedef unsigned long long u64;

__device__ __forceinline__ u64 pack2(float lo, float hi) {
    return (u64)__float_as_uint(lo) | ((u64)__float_as_uint(hi) << 32);
}

__device__ __forceinline__ u64 ffma2(u64 a, u64 b, u64 c) {
    u64 d;
    asm("fma.rn.f32x2 %0, %1, %2, %3;" : "=l"(d) : "l"(a), "l"(b), "l"(c));
    return d;
}

// mantissa_map: a = |v|+1e-7 (always normal); m = mantissa(a) in [1,2);
// M = m>=1.5 ? m/2 : m   (== reference piecewise map, values in [0.75,1.5))
__device__ __forceinline__ float mant_map(float v) {
    float a = fabsf(v) + 1e-7f;
    unsigned u = __float_as_uint(a);
    float m = __uint_as_float((u & 0x007FFFFFu) | 0x3F800000u);
    return (m >= 1.5f) ? m * 0.5f : m;
}

__global__ void __launch_bounds__(NT, 4)
appro_waconv_kernel(const float* __restrict__ x,
                    const float* __restrict__ w,
                    float* __restrict__ out)
{
    __shared__ u64 sh[SH_H * SH_W];      // (x, x/M1) packed, zero halo
    __shared__ u64 shw[7 * 8];           // (A, w-A), rows padded to 8 for LDS.128

    const int plane = blockIdx.x;            // b*NC + c : one full 56x56 plane
    const int c     = plane % NC;
    const int tid   = threadIdx.x;           // 0..223

    const float* __restrict__ xin = x + (size_t)plane * PLANE;

    // --- weights: A = w/M2, B = w - A (padded layout [7][8]) ---
    if (tid < 56) {
        int k = tid >> 3, j = tid & 7;
        u64 v = 0ull;
        if (j < 7) {
            float wv = w[c * 49 + k * 7 + j];
            float M2 = mant_map(wv);
            float A  = wv / M2;
            v = pack2(A, wv - A);
        }
        shw[tid] = v;
    }

    // --- zero the halo cells (pad rows/cols incl. col 62 pad) ---
    {
        // top 3 rows + bottom 3 rows: 6 * 63 = 378 cells
        for (int i = tid; i < 6 * SH_W; i += NT) {
            int r = i / SH_W, cc = i - (i / SH_W) * SH_W;
            int row = (r < 3) ? r : (SH_H - 3 + (r - 3));
            sh[row * SH_W + cc] = 0ull;
        }
        // left 3 + right 4 cols of the 56 interior rows: 7 * 56 = 392 cells
        for (int i = tid; i < 7 * HW; i += NT) {
            int r = i / 7, cc = i - (i / 7) * 7;
            int col = (cc < 3) ? cc : (59 + (cc - 3));
            sh[(r + 3) * SH_W + col] = 0ull;
        }
    }

    // --- interior: exactly 7 float2 loads per thread (1568 float2 total) ---
    {
        const float2* __restrict__ xin2 = (const float2*)xin;
#pragma unroll
        for (int i = 0; i < 7; ++i) {
            int idx = tid + i * NT;              // 0..1567
            int iy  = idx / 28;                  // row (28 float2 per row)
            int ix2 = idx - iy * 28;
            float2 v = __ldg(&xin2[idx]);
            float M1a = mant_map(v.x), M1b = mant_map(v.y);
            u64* dst = &sh[(iy + 3) * SH_W + (ix2 * 2 + 3)];
            dst[0] = pack2(v.x, __fdividef(v.x, M1a));
            dst[1] = pack2(v.y, __fdividef(v.y, M1b));
        }
    }
    __syncthreads();

    const int cg = tid & 7;                  // col group: cols [cg*7, cg*7+7)
    const int rg = tid >> 3;                 // row group: rows {rg*2, rg*2+1}

    u64 acc0[7], acc1[7];
#pragma unroll
    for (int cc = 0; cc < 7; ++cc) { acc0[cc] = 0ull; acc1[cc] = 0ull; }

    const u64* __restrict__ base = &sh[(rg * 2) * SH_W + cg * 7];
    const ulonglong2* __restrict__ wq = (const ulonglong2*)shw;

    // 8 input rows feed 2 output rows; weight rows via LDS.128 broadcast
#pragma unroll
    for (int r = 0; r < 8; ++r) {
        u64 p[13];
#pragma unroll
        for (int m = 0; m < 13; ++m) p[m] = base[r * SH_W + m];

        if (r <= 6) {   // weight row k = r -> acc0
            ulonglong2 q0 = wq[r*4+0], q1 = wq[r*4+1], q2 = wq[r*4+2], q3 = wq[r*4+3];
            u64 wj[7] = {q0.x, q0.y, q1.x, q1.y, q2.x, q2.y, q3.x};
#pragma unroll
            for (int j = 0; j < 7; ++j)
#pragma unroll
                for (int cc = 0; cc < 7; ++cc)
                    acc0[cc] = ffma2(p[cc + j], wj[j], acc0[cc]);
        }
        if (r >= 1) {   // weight row k = r-1 -> acc1
            int k = r - 1;
            ulonglong2 q0 = wq[k*4+0], q1 = wq[k*4+1], q2 = wq[k*4+2], q3 = wq[k*4+3];
            u64 wj[7] = {q0.x, q0.y, q1.x, q1.y, q2.x, q2.y, q3.x};
#pragma unroll
            for (int j = 0; j < 7; ++j)
#pragma unroll
                for (int cc = 0; cc < 7; ++cc)
                    acc1[cc] = ffma2(p[cc + j], wj[j], acc1[cc]);
        }
    }

    // --- stage outputs in smem (reuse sh) for coalesced global stores ---
    __syncthreads();                          // all mainloop reads done
    float* shf = (float*)sh;
#pragma unroll
    for (int cc = 0; cc < 7; ++cc) {
        float lo = __uint_as_float((unsigned)(acc0[cc] & 0xFFFFFFFFull));
        float hi = __uint_as_float((unsigned)(acc0[cc] >> 32));
        shf[(rg * 2) * HW + cg * 7 + cc] = lo + hi;
    }
#pragma unroll
    for (int cc = 0; cc < 7; ++cc) {
        float lo = __uint_as_float((unsigned)(acc1[cc] & 0xFFFFFFFFull));
        float hi = __uint_as_float((unsigned)(acc1[cc] >> 32));
        shf[(rg * 2 + 1) * HW + cg * 7 + cc] = lo + hi;
    }
    __syncthreads();

    float* __restrict__ o = out + (size_t)plane * PLANE;
#pragma unroll
    for (int i = 0; i < 14; ++i)              // 14 fully-coalesced STG.32
        o[tid + i * NT] = shf[tid + i * NT];
}

extern "C" void kernel_launch(void* const* d_in, const int* in_sizes, int n_in,
                              void* d_out, int out_size)
{
    const float* x = (const float*)d_in[0];      // (4,192,56,56) fp32
    const float* w = (const float*)d_in[1];      // (192,1,7,7)   fp32
    float* out = (float*)d_out;                  // (4,192,56,56) fp32

    appro_waconv_kernel<<<4 * NC, NT>>>(x, w, out);
}

// round 11
// speedup vs baseline: 1.4140x; 1.0017x over previous
#include <cuda_runtime.h>
#include <cstdint>

#define NC    192
#define HW    56
#define PLANE (HW*HW)
#define SH_W  63             // 62 used + 1 pad -> conflict-free for C=7 strips
#define SH_H  62
#define NT    224            // 28 row-groups (R=2) x 8 col-groups (C=7)

typedef unsigned long long u64;

__device__ __forceinline__ u64 pack2(float lo, float hi) {
    return (u64)__float_as_uint(lo) | ((u64)__float_as_uint(hi) << 32);
}

__device__ __forceinline__ u64 ffma2(u64 a, u64 b, u64 c) {
    u64 d;
    asm("fma.rn.f32x2 %0, %1, %2, %3;" : "=l"(d) : "l"(a), "l"(b), "l"(c));
    return d;
}

// mantissa_map: a = |v|+1e-7 (always normal); m = mantissa(a) in [1,2);
// M = m>=1.5 ? m/2 : m   (== reference piecewise map, values in [0.75,1.5))
__device__ __forceinline__ float mant_map(float v) {
    float a = fabsf(v) + 1e-7f;
    unsigned u = __float_as_uint(a);
    float m = __uint_as_float((u & 0x007FFFFFu) | 0x3F800000u);
    return (m >= 1.5f) ? m * 0.5f : m;
}

__global__ void __launch_bounds__(NT, 4)
appro_waconv_kernel(const float* __restrict__ x,
                    const float* __restrict__ w,
                    float* __restrict__ out)
{
    __shared__ u64 sh[SH_H * SH_W];      // (x, x/M1) packed, zero halo
    __shared__ u64 shw[7 * 8];           // (A, w-A), rows padded to 8 for LDS.128

    const int plane = blockIdx.x;            // b*NC + c : one full 56x56 plane
    const int c     = plane % NC;
    const int tid   = threadIdx.x;           // 0..223

    const float* __restrict__ xin = x + (size_t)plane * PLANE;

    // --- weights: A = w/M2, B = w - A (padded layout [7][8]) ---
    if (tid < 56) {
        int k = tid >> 3, j = tid & 7;
        u64 v = 0ull;
        if (j < 7) {
            float wv = w[c * 49 + k * 7 + j];
            float M2 = mant_map(wv);
            float A  = wv / M2;
            v = pack2(A, wv - A);
        }
        shw[tid] = v;
    }

    // --- zero the halo cells (pad rows/cols incl. col 62 pad) ---
    {
        // top 3 rows + bottom 3 rows: 6 * 63 = 378 cells
        for (int i = tid; i < 6 * SH_W; i += NT) {
            int r = i / SH_W, cc = i - (i / SH_W) * SH_W;
            int row = (r < 3) ? r : (SH_H - 3 + (r - 3));
            sh[row * SH_W + cc] = 0ull;
        }
        // left 3 + right 4 cols of the 56 interior rows: 7 * 56 = 392 cells
        for (int i = tid; i < 7 * HW; i += NT) {
            int r = i / 7, cc = i - (i / 7) * 7;
            int col = (cc < 3) ? cc : (59 + (cc - 3));
            sh[(r + 3) * SH_W + col] = 0ull;
        }
    }

    // --- interior: exactly 7 float2 loads per thread (1568 float2 total) ---
    {
        const float2* __restrict__ xin2 = (const float2*)xin;
#pragma unroll
        for (int i = 0; i < 7; ++i) {
            int idx = tid + i * NT;              // 0..1567
            int iy  = idx / 28;                  // row (28 float2 per row)
            int ix2 = idx - iy * 28;
            float2 v = __ldg(&xin2[idx]);
            float M1a = mant_map(v.x), M1b = mant_map(v.y);
            u64* dst = &sh[(iy + 3) * SH_W + (ix2 * 2 + 3)];
            dst[0] = pack2(v.x, __fdividef(v.x, M1a));
            dst[1] = pack2(v.y, __fdividef(v.y, M1b));
        }
    }
    __syncthreads();

    const int cg = tid & 7;                  // col group: cols [cg*7, cg*7+7)
    const int rg = tid >> 3;                 // row group: rows {rg*2, rg*2+1}

    u64 acc0[7], acc1[7];
#pragma unroll
    for (int cc = 0; cc < 7; ++cc) { acc0[cc] = 0ull; acc1[cc] = 0ull; }

    const u64* __restrict__ base = &sh[(rg * 2) * SH_W + cg * 7];
    const ulonglong2* __restrict__ wq = (const ulonglong2*)shw;

    // 8 input rows feed 2 output rows; weight rows via LDS.128 broadcast
#pragma unroll
    for (int r = 0; r < 8; ++r) {
        u64 p[13];
#pragma unroll
        for (int m = 0; m < 13; ++m) p[m] = base[r * SH_W + m];

        if (r <= 6) {   // weight row k = r -> acc0
            ulonglong2 q0 = wq[r*4+0], q1 = wq[r*4+1], q2 = wq[r*4+2], q3 = wq[r*4+3];
            u64 wj[7] = {q0.x, q0.y, q1.x, q1.y, q2.x, q2.y, q3.x};
#pragma unroll
            for (int j = 0; j < 7; ++j)
#pragma unroll
                for (int cc = 0; cc < 7; ++cc)
                    acc0[cc] = ffma2(p[cc + j], wj[j], acc0[cc]);
        }
        if (r >= 1) {   // weight row k = r-1 -> acc1
            int k = r - 1;
            ulonglong2 q0 = wq[k*4+0], q1 = wq[k*4+1], q2 = wq[k*4+2], q3 = wq[k*4+3];
            u64 wj[7] = {q0.x, q0.y, q1.x, q1.y, q2.x, q2.y, q3.x};
#pragma unroll
            for (int j = 0; j < 7; ++j)
#pragma unroll
                for (int cc = 0; cc < 7; ++cc)
                    acc1[cc] = ffma2(p[cc + j], wj[j], acc1[cc]);
        }
    }

    // --- stage outputs in smem (reuse sh) for coalesced global stores ---
    __syncthreads();                          // all mainloop reads done
    float* shf = (float*)sh;
#pragma unroll
    for (int cc = 0; cc < 7; ++cc) {
        float lo = __uint_as_float((unsigned)(acc0[cc] & 0xFFFFFFFFull));
        float hi = __uint_as_float((unsigned)(acc0[cc] >> 32));
        shf[(rg * 2) * HW + cg * 7 + cc] = lo + hi;
    }
#pragma unroll
    for (int cc = 0; cc < 7; ++cc) {
        float lo = __uint_as_float((unsigned)(acc1[cc] & 0xFFFFFFFFull));
        float hi = __uint_as_float((unsigned)(acc1[cc] >> 32));
        shf[(rg * 2 + 1) * HW + cg * 7 + cc] = lo + hi;
    }
    __syncthreads();

    float* __restrict__ o = out + (size_t)plane * PLANE;
#pragma unroll
    for (int i = 0; i < 14; ++i)              // 14 fully-coalesced STG.32
        o[tid + i * NT] = shf[tid + i * NT];
}

extern "C" void kernel_launch(void* const* d_in, const int* in_sizes, int n_in,
                              void* d_out, int out_size)
{
    const float* x = (const float*)d_in[0];      // (4,192,56,56) fp32
    const float* w = (const float*)d_in[1];      // (192,1,7,7)   fp32
    float* out = (float*)d_out;                  // (4,192,56,56) fp32

    appro_waconv_kernel<<<4 * NC, NT>>>(x, w, out);
}

// round 13
// speedup vs baseline: 1.4307x; 1.0118x over previous
#include <cuda_runtime.h>
#include <cstdint>

#define NC    192
#define HW    56
#define PLANE (HW*HW)
#define SH_W  63             // 62 used + 1 pad -> conflict-free for C=7 strips
#define SH_H  62
#define NT    224            // 28 row-groups (R=2) x 8 col-groups (C=7)

typedef unsigned long long u64;

__device__ __forceinline__ u64 pack2(float lo, float hi) {
    return (u64)__float_as_uint(lo) | ((u64)__float_as_uint(hi) << 32);
}

__device__ __forceinline__ u64 ffma2(u64 a, u64 b, u64 c) {
    u64 d;
    asm("fma.rn.f32x2 %0, %1, %2, %3;" : "=l"(d) : "l"(a), "l"(b), "l"(c));
    return d;
}

// mantissa_map: a = |v|+1e-7 (always normal); m = mantissa(a) in [1,2);
// M = m>=1.5 ? m/2 : m   (== reference piecewise map, values in [0.75,1.5))
__device__ __forceinline__ float mant_map(float v) {
    float a = fabsf(v) + 1e-7f;
    unsigned u = __float_as_uint(a);
    float m = __uint_as_float((u & 0x007FFFFFu) | 0x3F800000u);
    return (m >= 1.5f) ? m * 0.5f : m;
}

__global__ void __launch_bounds__(NT, 4)
appro_waconv_kernel(const float* __restrict__ x,
                    const float* __restrict__ w,
                    float* __restrict__ out)
{
    __shared__ u64 sh[SH_H * SH_W];      // (x, x/M1) packed, zero halo
    __shared__ u64 shw[7 * 8];           // (A, w-A), rows padded to 8 for LDS.128

    const int plane = blockIdx.x;            // b*NC + c : one full 56x56 plane
    const int c     = plane % NC;
    const int tid   = threadIdx.x;           // 0..223

    const float* __restrict__ xin = x + (size_t)plane * PLANE;

    // --- weights: A = w/M2, B = w - A (padded layout [7][8]) ---
    if (tid < 56) {
        int k = tid >> 3, j = tid & 7;
        u64 v = 0ull;
        if (j < 7) {
            float wv = w[c * 49 + k * 7 + j];
            float M2 = mant_map(wv);
            float A  = wv / M2;
            v = pack2(A, wv - A);
        }
        shw[tid] = v;
    }

    // --- zero the halo cells (pad rows/cols incl. col 62 pad) ---
    {
        // top 3 rows + bottom 3 rows: 6 * 63 = 378 cells
        for (int i = tid; i < 6 * SH_W; i += NT) {
            int r = i / SH_W, cc = i - (i / SH_W) * SH_W;
            int row = (r < 3) ? r : (SH_H - 3 + (r - 3));
            sh[row * SH_W + cc] = 0ull;
        }
        // left 3 + right 4 cols of the 56 interior rows: 7 * 56 = 392 cells
        for (int i = tid; i < 7 * HW; i += NT) {
            int r = i / 7, cc = i - (i / 7) * 7;
            int col = (cc < 3) ? cc : (59 + (cc - 3));
            sh[(r + 3) * SH_W + col] = 0ull;
        }
    }

    // --- interior: exactly 7 float2 loads per thread (1568 float2 total) ---
    {
        const float2* __restrict__ xin2 = (const float2*)xin;
#pragma unroll
        for (int i = 0; i < 7; ++i) {
            int idx = tid + i * NT;              // 0..1567
            int iy  = idx / 28;                  // row (28 float2 per row)
            int ix2 = idx - iy * 28;
            float2 v = __ldg(&xin2[idx]);
            float M1a = mant_map(v.x), M1b = mant_map(v.y);
            u64* dst = &sh[(iy + 3) * SH_W + (ix2 * 2 + 3)];
            dst[0] = pack2(v.x, __fdividef(v.x, M1a));
            dst[1] = pack2(v.y, __fdividef(v.y, M1b));
        }
    }
    __syncthreads();

    const int cg = tid & 7;                  // col group: cols [cg*7, cg*7+7)
    const int rg = tid >> 3;                 // row group: rows {rg*2, rg*2+1}

    u64 acc0[7], acc1[7];
#pragma unroll
    for (int cc = 0; cc < 7; ++cc) { acc0[cc] = 0ull; acc1[cc] = 0ull; }

    const u64* __restrict__ base = &sh[(rg * 2) * SH_W + cg * 7];
    const ulonglong2* __restrict__ wq = (const ulonglong2*)shw;

    // 8 input rows feed 2 output rows; weight rows via LDS.128 broadcast
#pragma unroll
    for (int r = 0; r < 8; ++r) {
        u64 p[13];
#pragma unroll
        for (int m = 0; m < 13; ++m) p[m] = base[r * SH_W + m];

        if (r <= 6) {   // weight row k = r -> acc0
            ulonglong2 q0 = wq[r*4+0], q1 = wq[r*4+1], q2 = wq[r*4+2], q3 = wq[r*4+3];
            u64 wj[7] = {q0.x, q0.y, q1.x, q1.y, q2.x, q2.y, q3.x};
#pragma unroll
            for (int j = 0; j < 7; ++j)
#pragma unroll
                for (int cc = 0; cc < 7; ++cc)
                    acc0[cc] = ffma2(p[cc + j], wj[j], acc0[cc]);
        }
        if (r >= 1) {   // weight row k = r-1 -> acc1
            int k = r - 1;
            ulonglong2 q0 = wq[k*4+0], q1 = wq[k*4+1], q2 = wq[k*4+2], q3 = wq[k*4+3];
            u64 wj[7] = {q0.x, q0.y, q1.x, q1.y, q2.x, q2.y, q3.x};
#pragma unroll
            for (int j = 0; j < 7; ++j)
#pragma unroll
                for (int cc = 0; cc < 7; ++cc)
                    acc1[cc] = ffma2(p[cc + j], wj[j], acc1[cc]);
        }
    }

    // --- stage outputs in smem (reuse sh) for coalesced global stores ---
    __syncthreads();                          // all mainloop reads done
    float* shf = (float*)sh;
#pragma unroll
    for (int cc = 0; cc < 7; ++cc) {
        float lo = __uint_as_float((unsigned)(acc0[cc] & 0xFFFFFFFFull));
        float hi = __uint_as_float((unsigned)(acc0[cc] >> 32));
        shf[(rg * 2) * HW + cg * 7 + cc] = lo + hi;
    }
#pragma unroll
    for (int cc = 0; cc < 7; ++cc) {
        float lo = __uint_as_float((unsigned)(acc1[cc] & 0xFFFFFFFFull));
        float hi = __uint_as_float((unsigned)(acc1[cc] >> 32));
        shf[(rg * 2 + 1) * HW + cg * 7 + cc] = lo + hi;
    }
    __syncthreads();

    float* __restrict__ o = out + (size_t)plane * PLANE;
#pragma unroll
    for (int i = 0; i < 14; ++i)              // 14 fully-coalesced STG.32
        o[tid + i * NT] = shf[tid + i * NT];
}

extern "C" void kernel_launch(void* const* d_in, const int* in_sizes, int n_in,
                              void* d_out, int out_size)
{
    const float* x = (const float*)d_in[0];      // (4,192,56,56) fp32
    const float* w = (const float*)d_in[1];      // (192,1,7,7)   fp32
    float* out = (float*)d_out;                  // (4,192,56,56) fp32

    appro_waconv_kernel<<<4 * NC, NT>>>(x, w, out);
}